// round 5
// baseline (speedup 1.0000x reference)
#include <cuda_runtime.h>

#define NN 50000
#define EE 800000
#define DH 64

// ---- scratch (device globals; no allocation allowed) ----
__device__ float g_h[NN * DH];
__device__ float g_P[NN * DH];
__device__ float g_Q[NN * DH];
__device__ float g_aggH[NN * DH];
__device__ float g_W2U[3 * DH * DH];   // W2 @ U1b per layer
__device__ float g_b2U[3 * DH];        // b2 @ U1b per layer
__device__ int   g_hist[NN];
__device__ int   g_off[NN + 1];        // CSR offsets (sorted by dst)
__device__ int   g_cur[NN];            // scatter cursors
__device__ int   g_rows[EE];           // src node per sorted edge

// ---- packed f32x2 fma helpers ----
#define FMA2(d, a, b) \
    asm volatile("fma.rn.f32x2 %0, %1, %2, %0;" : "+l"(d) : "l"(a), "l"(b))

__device__ __forceinline__ float unpack_add(unsigned long long v) {
    float lo, hi;
    asm("mov.b64 {%0,%1}, %2;" : "=f"(lo), "=f"(hi) : "l"(v));
    return lo + hi;
}

// swizzled transposed-weight layout: WsT[j][k], rotated by j to spread banks
__device__ __forceinline__ int swz(int j, int k) {
    return j * 64 + ((k + 4 * (j & 15)) & 63);
}

// stage 64x64 weight tile from gmem [k][j] into transposed swizzled smem
#define STAGE_WST(WST, SRC, T)                                              \
    _Pragma("unroll")                                                        \
    for (int it = 0; it < 16; it++) {                                        \
        int q = it * 256 + (T); int k = q >> 6, j = q & 63;                  \
        (WST)[swz(j, k)] = (SRC)[k * 64 + j];                                \
    }

// f32x2 GEMM: As[64][64] row-major (i,k) x WsT (j,k swizzled), micro 4r x 4j
// thread: tx in [0,16) -> cols j = tx + 16*jj ; i0 = 4*ty
#define GEMM2(AS, WST, I0, TX, ACCP)                                         \
    _Pragma("unroll 4")                                                      \
    for (int k0 = 0; k0 < 64; k0 += 4) {                                     \
        int wo = (k0 + 4 * (TX)) & 63;                                       \
        ulonglong2 wv0 = *(const ulonglong2*)&(WST)[((TX) +  0) * 64 + wo];  \
        ulonglong2 wv1 = *(const ulonglong2*)&(WST)[((TX) + 16) * 64 + wo];  \
        ulonglong2 wv2 = *(const ulonglong2*)&(WST)[((TX) + 32) * 64 + wo];  \
        ulonglong2 wv3 = *(const ulonglong2*)&(WST)[((TX) + 48) * 64 + wo];  \
        _Pragma("unroll")                                                    \
        for (int r = 0; r < 4; r++) {                                        \
            ulonglong2 av = *(const ulonglong2*)&(AS)[((I0) + r) * 64 + k0]; \
            FMA2(ACCP[r][0], av.x, wv0.x); FMA2(ACCP[r][0], av.y, wv0.y);    \
            FMA2(ACCP[r][1], av.x, wv1.x); FMA2(ACCP[r][1], av.y, wv1.y);    \
            FMA2(ACCP[r][2], av.x, wv2.x); FMA2(ACCP[r][2], av.y, wv2.y);    \
            FMA2(ACCP[r][3], av.x, wv3.x); FMA2(ACCP[r][3], av.y, wv3.y);    \
        }                                                                    \
    }

// classic f32 macro (still used by k_out)
#define GEMM_8x4(AS, I0, WS_PTR, WSTRIDE, ACC)                                  \
    _Pragma("unroll 4")                                                          \
    for (int k0 = 0; k0 < 64; k0 += 4) {                                         \
        float4 w0 = *(const float4*)&(WS_PTR)[(k0 + 0) * (WSTRIDE) + j0];        \
        float4 w1 = *(const float4*)&(WS_PTR)[(k0 + 1) * (WSTRIDE) + j0];        \
        float4 w2 = *(const float4*)&(WS_PTR)[(k0 + 2) * (WSTRIDE) + j0];        \
        float4 w3 = *(const float4*)&(WS_PTR)[(k0 + 3) * (WSTRIDE) + j0];        \
        _Pragma("unroll")                                                        \
        for (int r = 0; r < 8; r++) {                                            \
            float4 a4 = *(const float4*)&(AS)[((I0) + r) * DH + k0];             \
            ACC[r][0] = fmaf(a4.x, w0.x, ACC[r][0]);                             \
            ACC[r][1] = fmaf(a4.x, w0.y, ACC[r][1]);                             \
            ACC[r][2] = fmaf(a4.x, w0.z, ACC[r][2]);                             \
            ACC[r][3] = fmaf(a4.x, w0.w, ACC[r][3]);                             \
            ACC[r][0] = fmaf(a4.y, w1.x, ACC[r][0]);                             \
            ACC[r][1] = fmaf(a4.y, w1.y, ACC[r][1]);                             \
            ACC[r][2] = fmaf(a4.y, w1.z, ACC[r][2]);                             \
            ACC[r][3] = fmaf(a4.y, w1.w, ACC[r][3]);                             \
            ACC[r][0] = fmaf(a4.z, w2.x, ACC[r][0]);                             \
            ACC[r][1] = fmaf(a4.z, w2.y, ACC[r][1]);                             \
            ACC[r][2] = fmaf(a4.z, w2.z, ACC[r][2]);                             \
            ACC[r][3] = fmaf(a4.z, w2.w, ACC[r][3]);                             \
            ACC[r][0] = fmaf(a4.w, w3.x, ACC[r][0]);                             \
            ACC[r][1] = fmaf(a4.w, w3.y, ACC[r][1]);                             \
            ACC[r][2] = fmaf(a4.w, w3.z, ACC[r][2]);                             \
            ACC[r][3] = fmaf(a4.w, w3.w, ACC[r][3]);                             \
        }                                                                        \
    }

// =====================================================================
// Input projection: h = x @ in_w + in_b   ([N,3] @ [3,64])
// =====================================================================
__global__ void k_input(const float* __restrict__ x, const float* __restrict__ w,
                        const float* __restrict__ b, int n) {
    int t = blockIdx.x * blockDim.x + threadIdx.x;
    if (t >= n * DH) return;
    int i = t / DH, j = t % DH;
    float x0 = x[i * 3 + 0], x1 = x[i * 3 + 1], x2 = x[i * 3 + 2];
    g_h[t] = x0 * w[0 * DH + j] + x1 * w[1 * DH + j] + x2 * w[2 * DH + j] + b[j];
}

// =====================================================================
// Counting sort of edges by destination (built once, used 3 layers)
// =====================================================================
__global__ void k_zero_hist(int n) {
    int t = blockIdx.x * blockDim.x + threadIdx.x;
    if (t < n) g_hist[t] = 0;
}
__global__ void k_hist(const int* __restrict__ col, int e) {
    int t = blockIdx.x * blockDim.x + threadIdx.x;
    if (t < e) atomicAdd(&g_hist[col[t]], 1);
}
__global__ void k_scan(int n, int e) {
    __shared__ int ss[1024];
    int t = threadIdx.x;
    int chunk = (n + 1023) / 1024;
    int st = t * chunk;
    int fin = st + chunk < n ? st + chunk : n;
    int s = 0;
    for (int i = st; i < fin; i++) s += g_hist[i];
    ss[t] = s;
    __syncthreads();
    for (int o = 1; o < 1024; o <<= 1) {
        int v = (t >= o) ? ss[t - o] : 0;
        __syncthreads();
        ss[t] += v;
        __syncthreads();
    }
    int run = t ? ss[t - 1] : 0;
    for (int i = st; i < fin; i++) {
        int c = g_hist[i];
        g_off[i] = run; g_cur[i] = run;
        run += c;
    }
    if (t == 1023) g_off[n] = e;
}
__global__ void k_scatter(const int* __restrict__ row, const int* __restrict__ col,
                          int e) {
    int t = blockIdx.x * blockDim.x + threadIdx.x;
    if (t >= e) return;
    int c = col[t];
    int pos = atomicAdd(&g_cur[c], 1);
    g_rows[pos] = row[t];
}

// =====================================================================
// Per-layer precompute (all 3 layers in one launch, 1 block per layer):
// W2U[l] = W2[l] @ U1b[l], b2U[l] = b2[l] @ U1b[l]
// =====================================================================
__global__ void k_prep_all(const float* __restrict__ msg_w2,
                           const float* __restrict__ upd_w1,
                           const float* __restrict__ msg_b2) {
    int l = blockIdx.x;
    const float* w2  = msg_w2 + l * DH * DH;
    const float* u1b = upd_w1 + l * 2 * DH * DH + DH * DH;
    const float* b2  = msg_b2 + l * DH;
    __shared__ __align__(16) float W2s[DH * DH];
    __shared__ __align__(16) float U1s[DH * DH];
    __shared__ float b2s[DH];
    int t = threadIdx.x;
    for (int q = t; q < DH * DH / 4; q += 256) {
        *(float4*)&W2s[q * 4] = *(const float4*)&w2[q * 4];
        *(float4*)&U1s[q * 4] = *(const float4*)&u1b[q * 4];
    }
    if (t < DH) b2s[t] = b2[t];
    __syncthreads();
    for (int idx = t; idx < DH * DH; idx += 256) {
        int k = idx >> 6, j = idx & 63;
        float s = 0.f;
        #pragma unroll 8
        for (int m = 0; m < DH; m++) s = fmaf(W2s[k * DH + m], U1s[m * DH + j], s);
        g_W2U[l * DH * DH + idx] = s;
    }
    if (t < DH) {
        float s = 0.f;
        #pragma unroll 8
        for (int m = 0; m < DH; m++) s = fmaf(b2s[m], U1s[m * DH + t], s);
        g_b2U[l * DH + t] = s;
    }
}

// =====================================================================
// P = h @ W1[:64], Q = h @ W1[64:]   (f32x2 dual GEMM, 64-row tiles)
// =====================================================================
__global__ void __launch_bounds__(256, 4)
k_pq(const float* __restrict__ w1, int n) {
    __shared__ __align__(16) float As[64 * 64];
    __shared__ __align__(16) float WsT[64 * 64];
    int t = threadIdx.x, base = blockIdx.x * 64;
    int tx = t & 15, ty = t >> 4, i0 = ty * 4;

    #pragma unroll
    for (int it = 0; it < 4; it++) {
        int q = it * 256 + t;
        int i = q >> 4, j4 = (q & 15) * 4;
        float4 v = make_float4(0.f, 0.f, 0.f, 0.f);
        if (base + i < n) v = *(const float4*)&g_h[(base + i) * DH + j4];
        *(float4*)&As[i * 64 + j4] = v;
    }

    for (int pass = 0; pass < 2; pass++) {
        __syncthreads();
        STAGE_WST(WsT, w1 + pass * 64 * DH, t)
        __syncthreads();

        unsigned long long accp[4][4];
        #pragma unroll
        for (int r = 0; r < 4; r++)
            #pragma unroll
            for (int c = 0; c < 4; c++) accp[r][c] = 0ull;

        GEMM2(As, WsT, i0, tx, accp)

        float* dst = pass ? g_Q : g_P;
        #pragma unroll
        for (int r = 0; r < 4; r++) {
            int i = base + i0 + r;
            if (i < n) {
                #pragma unroll
                for (int jj = 0; jj < 4; jj++)
                    dst[i * DH + tx + 16 * jj] = unpack_add(accp[r][jj]);
            }
        }
    }
}

// =====================================================================
// CSR aggregation: aggH[v] = sum_{e: dst=v} relu(P[src_e] + Q[v] + b1)
// 16 lanes per node, Q+bias held in registers, no atomics.
// =====================================================================
__global__ void __launch_bounds__(256)
k_agg(const float* __restrict__ b1, int n) {
    int node = blockIdx.x * 16 + (threadIdx.x >> 4);
    int l4 = (threadIdx.x & 15) * 4;
    if (node >= n) return;
    int s = g_off[node], en = g_off[node + 1];
    float4 q = *(const float4*)&g_Q[node * DH + l4];
    float4 b = *(const float4*)&b1[l4];
    q.x += b.x; q.y += b.y; q.z += b.z; q.w += b.w;
    float4 acc = make_float4(0.f, 0.f, 0.f, 0.f);
    for (int e = s; e < en; e++) {
        int rr = g_rows[e];
        float4 p = *(const float4*)&g_P[rr * DH + l4];
        acc.x += fmaxf(p.x + q.x, 0.f);
        acc.y += fmaxf(p.y + q.y, 0.f);
        acc.z += fmaxf(p.z + q.z, 0.f);
        acc.w += fmaxf(p.w + q.w, 0.f);
    }
    *(float4*)&g_aggH[node * DH + l4] = acc;
}

// =====================================================================
// Node update (f32x2, 64-row tiles):
//   pre = h@U1a + aggH@W2U + deg*b2U + ub1 ;  h = relu(relu(pre)@U2 + ub2)
// =====================================================================
__global__ void __launch_bounds__(256, 4)
k_update(const float* __restrict__ u1a, const float* __restrict__ ub1,
         const float* __restrict__ u2, const float* __restrict__ ub2,
         int l, int n) {
    __shared__ __align__(16) float As[64 * 64];
    __shared__ __align__(16) float WsT[64 * 64];
    __shared__ float sb1[64], sb2[64], sbU[64];
    int t = threadIdx.x, base = blockIdx.x * 64;
    int tx = t & 15, ty = t >> 4, i0 = ty * 4;
    if (t < 64) { sb1[t] = ub1[t]; sb2[t] = ub2[t]; sbU[t] = g_b2U[l * DH + t]; }

    unsigned long long accp[4][4];
    #pragma unroll
    for (int r = 0; r < 4; r++)
        #pragma unroll
        for (int c = 0; c < 4; c++) accp[r][c] = 0ull;

    for (int pass = 0; pass < 2; pass++) {
        __syncthreads();
        const float* asrc = pass ? g_aggH : g_h;
        const float* wsrc = pass ? (g_W2U + l * DH * DH) : u1a;
        #pragma unroll
        for (int it = 0; it < 4; it++) {
            int q = it * 256 + t;
            int i = q >> 4, j4 = (q & 15) * 4;
            float4 v = make_float4(0.f, 0.f, 0.f, 0.f);
            if (base + i < n) v = *(const float4*)&asrc[(base + i) * DH + j4];
            *(float4*)&As[i * 64 + j4] = v;
        }
        STAGE_WST(WsT, wsrc, t)
        __syncthreads();

        GEMM2(As, WsT, i0, tx, accp)
    }
    __syncthreads();

    // hid = relu(pre) -> As
    #pragma unroll
    for (int r = 0; r < 4; r++) {
        int i = base + i0 + r;
        float dg = (i < n) ? (float)(g_off[i + 1] - g_off[i]) : 0.f;
        #pragma unroll
        for (int jj = 0; jj < 4; jj++) {
            int j = tx + 16 * jj;
            float v = unpack_add(accp[r][jj]) + dg * sbU[j] + sb1[j];
            As[(i0 + r) * 64 + j] = fmaxf(v, 0.f);
        }
    }
    STAGE_WST(WsT, u2, t)
    __syncthreads();

    unsigned long long accp2[4][4];
    #pragma unroll
    for (int r = 0; r < 4; r++)
        #pragma unroll
        for (int c = 0; c < 4; c++) accp2[r][c] = 0ull;

    GEMM2(As, WsT, i0, tx, accp2)

    #pragma unroll
    for (int r = 0; r < 4; r++) {
        int i = base + i0 + r;
        if (i < n) {
            #pragma unroll
            for (int jj = 0; jj < 4; jj++) {
                int j = tx + 16 * jj;
                g_h[i * DH + j] = fmaxf(unpack_add(accp2[r][jj]) + sb2[j], 0.f);
            }
        }
    }
}

// =====================================================================
// Output: out = h @ out_w + out_b   ([N,64] @ [64,128])
// =====================================================================
__global__ void __launch_bounds__(256, 4)
k_out(const float* __restrict__ ow, const float* __restrict__ ob,
      float* __restrict__ out, int n) {
    extern __shared__ float sm[];
    float* As = sm;            // [64][64]
    float* Ws = sm + 64 * DH;  // [64][128]
    int t = threadIdx.x;
    int base = blockIdx.x * 64;

    #pragma unroll
    for (int it = 0; it < 4; it++) {
        int q = it * 256 + t;
        int i = q >> 4, j4 = (q & 15) * 4;
        float4 v = make_float4(0.f, 0.f, 0.f, 0.f);
        if (base + i < n) v = *(const float4*)&g_h[(base + i) * DH + j4];
        *(float4*)&As[i * DH + j4] = v;
    }
    #pragma unroll
    for (int it = 0; it < 8; it++) {
        int q = it * 256 + t;
        int k = q >> 5, j4 = (q & 31) * 4;
        *(float4*)&Ws[k * 128 + j4] = *(const float4*)&ow[k * 128 + j4];
    }
    __syncthreads();

    int tx = t & 31, ty = t >> 5;
    int j0 = tx * 4, i0 = ty * 8;
    float acc[8][4];
    #pragma unroll
    for (int r = 0; r < 8; r++) {
        acc[r][0] = ob[j0 + 0]; acc[r][1] = ob[j0 + 1];
        acc[r][2] = ob[j0 + 2]; acc[r][3] = ob[j0 + 3];
    }

    GEMM_8x4(As, i0, Ws, 128, acc)

    #pragma unroll
    for (int r = 0; r < 8; r++) {
        int i = base + i0 + r;
        if (i < n)
            *(float4*)&out[i * 128 + j0] =
                make_float4(acc[r][0], acc[r][1], acc[r][2], acc[r][3]);
    }
}

// =====================================================================
// Launcher
// =====================================================================
extern "C" void kernel_launch(void* const* d_in, const int* in_sizes, int n_in,
                              void* d_out, int out_size) {
    const float* x      = (const float*)d_in[0];
    const int*   ei     = (const int*)  d_in[1];
    const float* in_w   = (const float*)d_in[2];
    const float* in_b   = (const float*)d_in[3];
    const float* msg_w1 = (const float*)d_in[4];
    const float* msg_b1 = (const float*)d_in[5];
    const float* msg_w2 = (const float*)d_in[6];
    const float* msg_b2 = (const float*)d_in[7];
    const float* upd_w1 = (const float*)d_in[8];
    const float* upd_b1 = (const float*)d_in[9];
    const float* upd_w2 = (const float*)d_in[10];
    const float* upd_b2 = (const float*)d_in[11];
    const float* out_w  = (const float*)d_in[12];
    const float* out_b  = (const float*)d_in[13];

    int n = in_sizes[0] / 3;
    int e = in_sizes[1] / 2;
    const int* row = ei;
    const int* col = ei + e;

    const int SMEM_OUT = (64 * DH + 64 * 128) * 4;  // 49152
    cudaFuncSetAttribute(k_out, cudaFuncAttributeMaxDynamicSharedMemorySize, SMEM_OUT);

    // build CSR (sorted by dst) once; reused by all 3 layers
    k_zero_hist<<<(n + 255) / 256, 256>>>(n);
    k_hist<<<(e + 255) / 256, 256>>>(col, e);
    k_scan<<<1, 1024>>>(n, e);
    k_scatter<<<(e + 255) / 256, 256>>>(row, col, e);

    k_prep_all<<<3, 256>>>(msg_w2, upd_w1, msg_b2);
    k_input<<<(n * DH + 255) / 256, 256>>>(x, in_w, in_b, n);

    int nb64 = (n + 63) / 64;
    for (int l = 0; l < 3; l++) {
        k_pq<<<nb64, 256>>>(msg_w1 + l * 2 * DH * DH, n);
        k_agg<<<(n + 15) / 16, 256>>>(msg_b1 + l * DH, n);
        k_update<<<nb64, 256>>>(upd_w1 + l * 2 * DH * DH, upd_b1 + l * DH,
                                upd_w2 + l * DH * DH, upd_b2 + l * DH, l, n);
    }
    k_out<<<nb64, 256, SMEM_OUT>>>(out_w, out_b, (float*)d_out, n);
}

// round 6
// speedup vs baseline: 1.4578x; 1.4578x over previous
#include <cuda_runtime.h>

#define NN 50000
#define EE 800000
#define DH 64

// ---- scratch (device globals; no allocation allowed) ----
__device__ float g_h[NN * DH];
__device__ float g_P[NN * DH];
__device__ float g_Q[NN * DH];
__device__ float g_aggH[NN * DH];
__device__ float g_W2U[3 * DH * DH];   // W2 @ U1b per layer
__device__ float g_b2U[3 * DH];        // b2 @ U1b per layer
__device__ int   g_hist[NN];
__device__ int   g_bsum[256];
__device__ int   g_bpre[256];
__device__ int   g_off[NN + 1];        // CSR offsets (sorted by dst)
__device__ int   g_cur[NN];            // scatter cursors
__device__ int   g_rows[EE];           // src node per sorted edge

// ---- proven f32 8x4 micro-kernel (lowest LDS per output) ----
#define GEMM_8x4(AS, I0, WS_PTR, WSTRIDE, ACC)                                  \
    _Pragma("unroll 4")                                                          \
    for (int k0 = 0; k0 < 64; k0 += 4) {                                         \
        float4 w0 = *(const float4*)&(WS_PTR)[(k0 + 0) * (WSTRIDE) + j0];        \
        float4 w1 = *(const float4*)&(WS_PTR)[(k0 + 1) * (WSTRIDE) + j0];        \
        float4 w2 = *(const float4*)&(WS_PTR)[(k0 + 2) * (WSTRIDE) + j0];        \
        float4 w3 = *(const float4*)&(WS_PTR)[(k0 + 3) * (WSTRIDE) + j0];        \
        _Pragma("unroll")                                                        \
        for (int r = 0; r < 8; r++) {                                            \
            float4 a4 = *(const float4*)&(AS)[((I0) + r) * DH + k0];             \
            ACC[r][0] = fmaf(a4.x, w0.x, ACC[r][0]);                             \
            ACC[r][1] = fmaf(a4.x, w0.y, ACC[r][1]);                             \
            ACC[r][2] = fmaf(a4.x, w0.z, ACC[r][2]);                             \
            ACC[r][3] = fmaf(a4.x, w0.w, ACC[r][3]);                             \
            ACC[r][0] = fmaf(a4.y, w1.x, ACC[r][0]);                             \
            ACC[r][1] = fmaf(a4.y, w1.y, ACC[r][1]);                             \
            ACC[r][2] = fmaf(a4.y, w1.z, ACC[r][2]);                             \
            ACC[r][3] = fmaf(a4.y, w1.w, ACC[r][3]);                             \
            ACC[r][0] = fmaf(a4.z, w2.x, ACC[r][0]);                             \
            ACC[r][1] = fmaf(a4.z, w2.y, ACC[r][1]);                             \
            ACC[r][2] = fmaf(a4.z, w2.z, ACC[r][2]);                             \
            ACC[r][3] = fmaf(a4.z, w2.w, ACC[r][3]);                             \
            ACC[r][0] = fmaf(a4.w, w3.x, ACC[r][0]);                             \
            ACC[r][1] = fmaf(a4.w, w3.y, ACC[r][1]);                             \
            ACC[r][2] = fmaf(a4.w, w3.z, ACC[r][2]);                             \
            ACC[r][3] = fmaf(a4.w, w3.w, ACC[r][3]);                             \
        }                                                                        \
    }

// =====================================================================
// Input projection: h = x @ in_w + in_b   ([N,3] @ [3,64])
// =====================================================================
__global__ void k_input(const float* __restrict__ x, const float* __restrict__ w,
                        const float* __restrict__ b, int n) {
    int t = blockIdx.x * blockDim.x + threadIdx.x;
    if (t >= n * DH) return;
    int i = t / DH, j = t % DH;
    float x0 = x[i * 3 + 0], x1 = x[i * 3 + 1], x2 = x[i * 3 + 2];
    g_h[t] = x0 * w[0 * DH + j] + x1 * w[1 * DH + j] + x2 * w[2 * DH + j] + b[j];
}

// =====================================================================
// Counting sort of edges by destination (built once, used 3 layers)
// =====================================================================
__global__ void k_zero_hist(int n) {
    int t = blockIdx.x * blockDim.x + threadIdx.x;
    if (t < n) g_hist[t] = 0;
}
__global__ void k_hist(const int* __restrict__ col, int e) {
    int t = blockIdx.x * blockDim.x + threadIdx.x;
    if (t < e) atomicAdd(&g_hist[col[t]], 1);
}
// parallel 3-stage scan
__global__ void k_blocksum(int n) {
    __shared__ int ss[256];
    int t = threadIdx.x, i = blockIdx.x * 256 + t;
    ss[t] = (i < n) ? g_hist[i] : 0;
    __syncthreads();
    for (int o = 128; o > 0; o >>= 1) {
        if (t < o) ss[t] += ss[t + o];
        __syncthreads();
    }
    if (t == 0) g_bsum[blockIdx.x] = ss[0];
}
__global__ void k_scan_bsum(int nb) {
    __shared__ int ss[256];
    int t = threadIdx.x;
    int v0 = (t < nb) ? g_bsum[t] : 0;
    ss[t] = v0;
    __syncthreads();
    for (int o = 1; o < 256; o <<= 1) {
        int v = (t >= o) ? ss[t - o] : 0;
        __syncthreads();
        ss[t] += v;
        __syncthreads();
    }
    g_bpre[t] = ss[t] - v0;  // exclusive prefix of block sums
}
__global__ void k_offsets(int n, int e) {
    __shared__ int ss[256];
    int t = threadIdx.x, i = blockIdx.x * 256 + t;
    int h = (i < n) ? g_hist[i] : 0;
    ss[t] = h;
    __syncthreads();
    for (int o = 1; o < 256; o <<= 1) {
        int v = (t >= o) ? ss[t - o] : 0;
        __syncthreads();
        ss[t] += v;
        __syncthreads();
    }
    int excl = ss[t] - h + g_bpre[blockIdx.x];
    if (i < n) {
        g_off[i] = excl; g_cur[i] = excl;
        if (i == n - 1) g_off[n] = e;
    }
}
__global__ void k_scatter(const int* __restrict__ row, const int* __restrict__ col,
                          int e) {
    int t = blockIdx.x * blockDim.x + threadIdx.x;
    if (t >= e) return;
    int c = col[t];
    int pos = atomicAdd(&g_cur[c], 1);
    g_rows[pos] = row[t];
}

// =====================================================================
// Per-layer precompute (1 block per layer):
// W2U[l] = W2[l] @ U1b[l], b2U[l] = b2[l] @ U1b[l]
// =====================================================================
__global__ void k_prep_all(const float* __restrict__ msg_w2,
                           const float* __restrict__ upd_w1,
                           const float* __restrict__ msg_b2) {
    int l = blockIdx.x;
    const float* w2  = msg_w2 + l * DH * DH;
    const float* u1b = upd_w1 + l * 2 * DH * DH + DH * DH;
    const float* b2  = msg_b2 + l * DH;
    __shared__ __align__(16) float W2s[DH * DH];
    __shared__ __align__(16) float U1s[DH * DH];
    __shared__ float b2s[DH];
    int t = threadIdx.x;
    for (int q = t; q < DH * DH / 4; q += 256) {
        *(float4*)&W2s[q * 4] = *(const float4*)&w2[q * 4];
        *(float4*)&U1s[q * 4] = *(const float4*)&u1b[q * 4];
    }
    if (t < DH) b2s[t] = b2[t];
    __syncthreads();
    for (int idx = t; idx < DH * DH; idx += 256) {
        int k = idx >> 6, j = idx & 63;
        float s = 0.f;
        #pragma unroll 8
        for (int m = 0; m < DH; m++) s = fmaf(W2s[k * DH + m], U1s[m * DH + j], s);
        g_W2U[l * DH * DH + idx] = s;
    }
    if (t < DH) {
        float s = 0.f;
        #pragma unroll 8
        for (int m = 0; m < DH; m++) s = fmaf(b2s[m], U1s[m * DH + t], s);
        g_b2U[l * DH + t] = s;
    }
}

// =====================================================================
// P or Q = h @ W1 half.  blockIdx.y selects pass -> 2x grid, better occupancy
// =====================================================================
__global__ void __launch_bounds__(256, 4)
k_pq(const float* __restrict__ w1, int n) {
    extern __shared__ float sm[];
    float* As = sm;             // [128][64]
    float* Ws = sm + 128 * DH;  // [64][64]
    int t = threadIdx.x;
    int base = blockIdx.x * 128;
    int pass = blockIdx.y;

    #pragma unroll
    for (int it = 0; it < 8; it++) {
        int q = it * 256 + t;
        int i = q >> 4, j4 = (q & 15) * 4;
        float4 v = make_float4(0.f, 0.f, 0.f, 0.f);
        if (base + i < n) v = *(const float4*)&g_h[(base + i) * DH + j4];
        *(float4*)&As[i * DH + j4] = v;
    }
    const float* wsrc = w1 + pass * 64 * DH;
    #pragma unroll
    for (int it = 0; it < 4; it++) {
        int q = it * 256 + t;
        int k = q >> 4, j4 = (q & 15) * 4;
        *(float4*)&Ws[k * DH + j4] = *(const float4*)&wsrc[k * DH + j4];
    }
    __syncthreads();

    int tx = t & 15, ty = t >> 4;
    int j0 = tx * 4, i0 = ty * 8;

    float acc[8][4];
    #pragma unroll
    for (int r = 0; r < 8; r++)
        #pragma unroll
        for (int c = 0; c < 4; c++) acc[r][c] = 0.f;

    GEMM_8x4(As, i0, Ws, DH, acc)

    float* dst = pass ? g_Q : g_P;
    #pragma unroll
    for (int r = 0; r < 8; r++) {
        int i = base + i0 + r;
        if (i < n)
            *(float4*)&dst[i * DH + j0] =
                make_float4(acc[r][0], acc[r][1], acc[r][2], acc[r][3]);
    }
}

// =====================================================================
// CSR aggregation: aggH[v] = sum_{e: dst=v} relu(P[src_e] + Q[v] + b1)
// 16 lanes per node, unroll-4 pipelined gathers (MLP 4), no atomics.
// =====================================================================
__global__ void __launch_bounds__(256)
k_agg(const float* __restrict__ b1, int n) {
    int node = blockIdx.x * 16 + (threadIdx.x >> 4);
    int l4 = (threadIdx.x & 15) * 4;
    if (node >= n) return;
    int s = g_off[node], en = g_off[node + 1];
    float4 q = *(const float4*)&g_Q[node * DH + l4];
    float4 b = *(const float4*)&b1[l4];
    q.x += b.x; q.y += b.y; q.z += b.z; q.w += b.w;
    float4 acc = make_float4(0.f, 0.f, 0.f, 0.f);
    int e = s;
    for (; e + 4 <= en; e += 4) {
        int r0 = __ldg(&g_rows[e + 0]);
        int r1 = __ldg(&g_rows[e + 1]);
        int r2 = __ldg(&g_rows[e + 2]);
        int r3 = __ldg(&g_rows[e + 3]);
        float4 p0 = *(const float4*)&g_P[r0 * DH + l4];
        float4 p1 = *(const float4*)&g_P[r1 * DH + l4];
        float4 p2 = *(const float4*)&g_P[r2 * DH + l4];
        float4 p3 = *(const float4*)&g_P[r3 * DH + l4];
        acc.x += fmaxf(p0.x + q.x, 0.f) + fmaxf(p1.x + q.x, 0.f)
               + fmaxf(p2.x + q.x, 0.f) + fmaxf(p3.x + q.x, 0.f);
        acc.y += fmaxf(p0.y + q.y, 0.f) + fmaxf(p1.y + q.y, 0.f)
               + fmaxf(p2.y + q.y, 0.f) + fmaxf(p3.y + q.y, 0.f);
        acc.z += fmaxf(p0.z + q.z, 0.f) + fmaxf(p1.z + q.z, 0.f)
               + fmaxf(p2.z + q.z, 0.f) + fmaxf(p3.z + q.z, 0.f);
        acc.w += fmaxf(p0.w + q.w, 0.f) + fmaxf(p1.w + q.w, 0.f)
               + fmaxf(p2.w + q.w, 0.f) + fmaxf(p3.w + q.w, 0.f);
    }
    for (; e < en; e++) {
        int rr = __ldg(&g_rows[e]);
        float4 p = *(const float4*)&g_P[rr * DH + l4];
        acc.x += fmaxf(p.x + q.x, 0.f);
        acc.y += fmaxf(p.y + q.y, 0.f);
        acc.z += fmaxf(p.z + q.z, 0.f);
        acc.w += fmaxf(p.w + q.w, 0.f);
    }
    *(float4*)&g_aggH[node * DH + l4] = acc;
}

// =====================================================================
// Node update:
//   pre = h@U1a + aggH@W2U + deg*b2U + ub1 ;  h = relu(relu(pre)@U2 + ub2)
// =====================================================================
__global__ void __launch_bounds__(256, 4)
k_update(const float* __restrict__ u1a, const float* __restrict__ ub1,
         const float* __restrict__ u2, const float* __restrict__ ub2,
         int l, int n) {
    extern __shared__ float sm[];
    float* As   = sm;             // [128][64]
    float* Ws   = sm + 128 * DH;  // [64][64]
    float* b1s  = Ws + 64 * DH;
    float* b2s  = b1s + 64;
    float* b2Us = b2s + 64;
    int t = threadIdx.x;
    int base = blockIdx.x * 128;
    if (t < 64) { b1s[t] = ub1[t]; b2s[t] = ub2[t]; b2Us[t] = g_b2U[l * DH + t]; }

    int tx = t & 15, ty = t >> 4;
    int j0 = tx * 4, i0 = ty * 8;

    float acc[8][4];
    #pragma unroll
    for (int r = 0; r < 8; r++)
        #pragma unroll
        for (int c = 0; c < 4; c++) acc[r][c] = 0.f;

    for (int pass = 0; pass < 2; pass++) {
        __syncthreads();
        const float* a_src = pass ? g_aggH : g_h;
        const float* wsrc  = pass ? (g_W2U + l * DH * DH) : u1a;
        #pragma unroll
        for (int it = 0; it < 8; it++) {
            int q = it * 256 + t;
            int i = q >> 4, j4 = (q & 15) * 4;
            float4 v = make_float4(0.f, 0.f, 0.f, 0.f);
            if (base + i < n) v = *(const float4*)&a_src[(base + i) * DH + j4];
            *(float4*)&As[i * DH + j4] = v;
        }
        #pragma unroll
        for (int it = 0; it < 4; it++) {
            int q = it * 256 + t;
            int k = q >> 4, j4 = (q & 15) * 4;
            *(float4*)&Ws[k * DH + j4] = *(const float4*)&wsrc[k * DH + j4];
        }
        __syncthreads();

        GEMM_8x4(As, i0, Ws, DH, acc)
    }
    __syncthreads();

    // hid = relu(acc + deg*b2U + ub1) -> As
    #pragma unroll
    for (int r = 0; r < 8; r++) {
        int i = base + i0 + r;
        float dg = (i < n) ? (float)(g_off[i + 1] - g_off[i]) : 0.f;
        float4 hv;
        hv.x = fmaxf(fmaf(dg, b2Us[j0 + 0], acc[r][0]) + b1s[j0 + 0], 0.f);
        hv.y = fmaxf(fmaf(dg, b2Us[j0 + 1], acc[r][1]) + b1s[j0 + 1], 0.f);
        hv.z = fmaxf(fmaf(dg, b2Us[j0 + 2], acc[r][2]) + b1s[j0 + 2], 0.f);
        hv.w = fmaxf(fmaf(dg, b2Us[j0 + 3], acc[r][3]) + b1s[j0 + 3], 0.f);
        *(float4*)&As[(i0 + r) * DH + j0] = hv;
    }
    #pragma unroll
    for (int it = 0; it < 4; it++) {
        int q = it * 256 + t;
        int k = q >> 4, j4 = (q & 15) * 4;
        *(float4*)&Ws[k * DH + j4] = *(const float4*)&u2[k * DH + j4];
    }
    __syncthreads();

    float acc2[8][4];
    #pragma unroll
    for (int r = 0; r < 8; r++) {
        acc2[r][0] = b2s[j0 + 0]; acc2[r][1] = b2s[j0 + 1];
        acc2[r][2] = b2s[j0 + 2]; acc2[r][3] = b2s[j0 + 3];
    }

    GEMM_8x4(As, i0, Ws, DH, acc2)

    #pragma unroll
    for (int r = 0; r < 8; r++) {
        int i = base + i0 + r;
        if (i < n) {
            float4 hv;
            hv.x = fmaxf(acc2[r][0], 0.f); hv.y = fmaxf(acc2[r][1], 0.f);
            hv.z = fmaxf(acc2[r][2], 0.f); hv.w = fmaxf(acc2[r][3], 0.f);
            *(float4*)&g_h[i * DH + j0] = hv;
        }
    }
}

// =====================================================================
// Output: out = h @ out_w + out_b   ([N,64] @ [64,128])
// =====================================================================
__global__ void __launch_bounds__(256, 4)
k_out(const float* __restrict__ ow, const float* __restrict__ ob,
      float* __restrict__ out, int n) {
    extern __shared__ float sm[];
    float* As = sm;            // [64][64]
    float* Ws = sm + 64 * DH;  // [64][128]
    int t = threadIdx.x;
    int base = blockIdx.x * 64;

    #pragma unroll
    for (int it = 0; it < 4; it++) {
        int q = it * 256 + t;
        int i = q >> 4, j4 = (q & 15) * 4;
        float4 v = make_float4(0.f, 0.f, 0.f, 0.f);
        if (base + i < n) v = *(const float4*)&g_h[(base + i) * DH + j4];
        *(float4*)&As[i * DH + j4] = v;
    }
    #pragma unroll
    for (int it = 0; it < 8; it++) {
        int q = it * 256 + t;
        int k = q >> 5, j4 = (q & 31) * 4;
        *(float4*)&Ws[k * 128 + j4] = *(const float4*)&ow[k * 128 + j4];
    }
    __syncthreads();

    int tx = t & 31, ty = t >> 5;
    int j0 = tx * 4, i0 = ty * 8;
    float acc[8][4];
    #pragma unroll
    for (int r = 0; r < 8; r++) {
        acc[r][0] = ob[j0 + 0]; acc[r][1] = ob[j0 + 1];
        acc[r][2] = ob[j0 + 2]; acc[r][3] = ob[j0 + 3];
    }

    GEMM_8x4(As, i0, Ws, 128, acc)

    #pragma unroll
    for (int r = 0; r < 8; r++) {
        int i = base + i0 + r;
        if (i < n)
            *(float4*)&out[i * 128 + j0] =
                make_float4(acc[r][0], acc[r][1], acc[r][2], acc[r][3]);
    }
}

// =====================================================================
// Launcher
// =====================================================================
extern "C" void kernel_launch(void* const* d_in, const int* in_sizes, int n_in,
                              void* d_out, int out_size) {
    const float* x      = (const float*)d_in[0];
    const int*   ei     = (const int*)  d_in[1];
    const float* in_w   = (const float*)d_in[2];
    const float* in_b   = (const float*)d_in[3];
    const float* msg_w1 = (const float*)d_in[4];
    const float* msg_b1 = (const float*)d_in[5];
    const float* msg_w2 = (const float*)d_in[6];
    const float* msg_b2 = (const float*)d_in[7];
    const float* upd_w1 = (const float*)d_in[8];
    const float* upd_b1 = (const float*)d_in[9];
    const float* upd_w2 = (const float*)d_in[10];
    const float* upd_b2 = (const float*)d_in[11];
    const float* out_w  = (const float*)d_in[12];
    const float* out_b  = (const float*)d_in[13];

    int n = in_sizes[0] / 3;
    int e = in_sizes[1] / 2;
    const int* row = ei;
    const int* col = ei + e;

    const int SMEM_PQ  = (128 * DH + 64 * DH) * 4;           // 49152
    const int SMEM_UPD = (128 * DH + 64 * DH + 192) * 4;     // 49920
    const int SMEM_OUT = (64 * DH + 64 * 128) * 4;           // 49152

    cudaFuncSetAttribute(k_pq,     cudaFuncAttributeMaxDynamicSharedMemorySize, SMEM_PQ);
    cudaFuncSetAttribute(k_update, cudaFuncAttributeMaxDynamicSharedMemorySize, SMEM_UPD);
    cudaFuncSetAttribute(k_out,    cudaFuncAttributeMaxDynamicSharedMemorySize, SMEM_OUT);

    // build CSR (sorted by dst) once; reused by all 3 layers
    int nbn = (n + 255) / 256;   // 196 blocks
    k_zero_hist<<<nbn, 256>>>(n);
    k_hist<<<(e + 255) / 256, 256>>>(col, e);
    k_blocksum<<<nbn, 256>>>(n);
    k_scan_bsum<<<1, 256>>>(nbn);
    k_offsets<<<nbn, 256>>>(n, e);
    k_scatter<<<(e + 255) / 256, 256>>>(row, col, e);

    k_prep_all<<<3, 256>>>(msg_w2, upd_w1, msg_b2);
    k_input<<<(n * DH + 255) / 256, 256>>>(x, in_w, in_b, n);

    int nb128 = (n + 127) / 128;
    for (int l = 0; l < 3; l++) {
        k_pq<<<dim3(nb128, 2), 256, SMEM_PQ>>>(msg_w1 + l * 2 * DH * DH, n);
        k_agg<<<(n + 15) / 16, 256>>>(msg_b1 + l * DH, n);
        k_update<<<nb128, 256, SMEM_UPD>>>(upd_w1 + l * 2 * DH * DH, upd_b1 + l * DH,
                                           upd_w2 + l * DH * DH, upd_b2 + l * DH, l, n);
    }
    k_out<<<(n + 63) / 64, 256, SMEM_OUT>>>(out_w, out_b, (float*)d_out, n);
}

// round 7
// speedup vs baseline: 1.5521x; 1.0646x over previous
#include <cuda_runtime.h>

#define NN 50000
#define EE 800000
#define DH 64

// ---- scratch (device globals; no allocation allowed) ----
__device__ float g_h[NN * DH];
__device__ float g_P[NN * DH];
__device__ float g_Q[NN * DH];
__device__ float g_aggH[NN * DH];
__device__ float g_W2U[3 * DH * DH];   // W2 @ U1b per layer
__device__ float g_b2U[3 * DH];        // b2 @ U1b per layer
__device__ float g_CWP[3 * DH];        // in_w @ W1a[0]  (3x64)
__device__ float g_CWQ[3 * DH];        // in_w @ W1b[0]
__device__ float g_cbP[DH];            // in_b @ W1a[0]
__device__ float g_cbQ[DH];            // in_b @ W1b[0]
__device__ int   g_hist[NN];
__device__ int   g_bsum[256];
__device__ int   g_bpre[256];
__device__ int   g_off[NN + 1];        // CSR offsets (sorted by dst)
__device__ int   g_cur[NN];            // scatter cursors
__device__ int   g_rows[EE];           // src node per sorted edge

// ---- proven f32 8x4 micro-kernel ----
#define GEMM_8x4(AS, I0, WS_PTR, WSTRIDE, ACC)                                  \
    _Pragma("unroll 4")                                                          \
    for (int k0 = 0; k0 < 64; k0 += 4) {                                         \
        float4 w0 = *(const float4*)&(WS_PTR)[(k0 + 0) * (WSTRIDE) + j0];        \
        float4 w1 = *(const float4*)&(WS_PTR)[(k0 + 1) * (WSTRIDE) + j0];        \
        float4 w2 = *(const float4*)&(WS_PTR)[(k0 + 2) * (WSTRIDE) + j0];        \
        float4 w3 = *(const float4*)&(WS_PTR)[(k0 + 3) * (WSTRIDE) + j0];        \
        _Pragma("unroll")                                                        \
        for (int r = 0; r < 8; r++) {                                            \
            float4 a4 = *(const float4*)&(AS)[((I0) + r) * DH + k0];             \
            ACC[r][0] = fmaf(a4.x, w0.x, ACC[r][0]);                             \
            ACC[r][1] = fmaf(a4.x, w0.y, ACC[r][1]);                             \
            ACC[r][2] = fmaf(a4.x, w0.z, ACC[r][2]);                             \
            ACC[r][3] = fmaf(a4.x, w0.w, ACC[r][3]);                             \
            ACC[r][0] = fmaf(a4.y, w1.x, ACC[r][0]);                             \
            ACC[r][1] = fmaf(a4.y, w1.y, ACC[r][1]);                             \
            ACC[r][2] = fmaf(a4.y, w1.z, ACC[r][2]);                             \
            ACC[r][3] = fmaf(a4.y, w1.w, ACC[r][3]);                             \
            ACC[r][0] = fmaf(a4.z, w2.x, ACC[r][0]);                             \
            ACC[r][1] = fmaf(a4.z, w2.y, ACC[r][1]);                             \
            ACC[r][2] = fmaf(a4.z, w2.z, ACC[r][2]);                             \
            ACC[r][3] = fmaf(a4.z, w2.w, ACC[r][3]);                             \
            ACC[r][0] = fmaf(a4.w, w3.x, ACC[r][0]);                             \
            ACC[r][1] = fmaf(a4.w, w3.y, ACC[r][1]);                             \
            ACC[r][2] = fmaf(a4.w, w3.z, ACC[r][2]);                             \
            ACC[r][3] = fmaf(a4.w, w3.w, ACC[r][3]);                             \
        }                                                                        \
    }

// stage a 64x64 weight tile (row-major) into smem, float4
#define STAGE_W(WS, SRC, T)                                                     \
    _Pragma("unroll")                                                            \
    for (int it = 0; it < 4; it++) {                                             \
        int q = it * 256 + (T);                                                  \
        int k = q >> 4, j4 = (q & 15) * 4;                                       \
        *(float4*)&(WS)[k * DH + j4] = *(const float4*)&(SRC)[k * DH + j4];      \
    }

// =====================================================================
// Fused input: h = x@in_w + in_b ; P0 = x@CWP + cbP ; Q0 = x@CWQ + cbQ
// (valid because the input projection is linear — composites from k_prep)
// =====================================================================
__global__ void k_input(const float* __restrict__ x, const float* __restrict__ w,
                        const float* __restrict__ b, int n) {
    int t = blockIdx.x * blockDim.x + threadIdx.x;
    if (t >= n * DH) return;
    int i = t / DH, j = t % DH;
    float x0 = x[i * 3 + 0], x1 = x[i * 3 + 1], x2 = x[i * 3 + 2];
    g_h[t] = fmaf(x0, w[0 * DH + j], fmaf(x1, w[1 * DH + j],
             fmaf(x2, w[2 * DH + j], b[j])));
    g_P[t] = fmaf(x0, g_CWP[0 * DH + j], fmaf(x1, g_CWP[1 * DH + j],
             fmaf(x2, g_CWP[2 * DH + j], g_cbP[j])));
    g_Q[t] = fmaf(x0, g_CWQ[0 * DH + j], fmaf(x1, g_CWQ[1 * DH + j],
             fmaf(x2, g_CWQ[2 * DH + j], g_cbQ[j])));
}

// =====================================================================
// Counting sort of edges by destination (built once, used 3 layers)
// =====================================================================
__global__ void k_zero_hist(int n) {
    int t = blockIdx.x * blockDim.x + threadIdx.x;
    if (t < n) g_hist[t] = 0;
}
__global__ void k_hist(const int* __restrict__ col, int e) {
    int t = blockIdx.x * blockDim.x + threadIdx.x;
    if (t < e) atomicAdd(&g_hist[col[t]], 1);
}
__global__ void k_blocksum(int n) {
    __shared__ int ss[256];
    int t = threadIdx.x, i = blockIdx.x * 256 + t;
    ss[t] = (i < n) ? g_hist[i] : 0;
    __syncthreads();
    for (int o = 128; o > 0; o >>= 1) {
        if (t < o) ss[t] += ss[t + o];
        __syncthreads();
    }
    if (t == 0) g_bsum[blockIdx.x] = ss[0];
}
__global__ void k_scan_bsum(int nb) {
    __shared__ int ss[256];
    int t = threadIdx.x;
    int v0 = (t < nb) ? g_bsum[t] : 0;
    ss[t] = v0;
    __syncthreads();
    for (int o = 1; o < 256; o <<= 1) {
        int v = (t >= o) ? ss[t - o] : 0;
        __syncthreads();
        ss[t] += v;
        __syncthreads();
    }
    g_bpre[t] = ss[t] - v0;
}
__global__ void k_offsets(int n, int e) {
    __shared__ int ss[256];
    int t = threadIdx.x, i = blockIdx.x * 256 + t;
    int h = (i < n) ? g_hist[i] : 0;
    ss[t] = h;
    __syncthreads();
    for (int o = 1; o < 256; o <<= 1) {
        int v = (t >= o) ? ss[t - o] : 0;
        __syncthreads();
        ss[t] += v;
        __syncthreads();
    }
    int excl = ss[t] - h + g_bpre[blockIdx.x];
    if (i < n) {
        g_off[i] = excl; g_cur[i] = excl;
        if (i == n - 1) g_off[n] = e;
    }
}
__global__ void k_scatter(const int* __restrict__ row, const int* __restrict__ col,
                          int e) {
    int t = blockIdx.x * blockDim.x + threadIdx.x;
    if (t >= e) return;
    int c = col[t];
    int pos = atomicAdd(&g_cur[c], 1);
    g_rows[pos] = row[t];
}

// =====================================================================
// Precompute: blocks 0..2 -> W2U[l], b2U[l]; block 3 -> input composites
// =====================================================================
__global__ void k_prep_all(const float* __restrict__ msg_w2,
                           const float* __restrict__ upd_w1,
                           const float* __restrict__ msg_b2,
                           const float* __restrict__ msg_w1,
                           const float* __restrict__ in_w,
                           const float* __restrict__ in_b) {
    int t = threadIdx.x;
    if (blockIdx.x < 3) {
        int l = blockIdx.x;
        const float* w2  = msg_w2 + l * DH * DH;
        const float* u1b = upd_w1 + l * 2 * DH * DH + DH * DH;
        const float* b2  = msg_b2 + l * DH;
        __shared__ __align__(16) float W2s[DH * DH];
        __shared__ __align__(16) float U1s[DH * DH];
        __shared__ float b2s[DH];
        for (int q = t; q < DH * DH / 4; q += 256) {
            *(float4*)&W2s[q * 4] = *(const float4*)&w2[q * 4];
            *(float4*)&U1s[q * 4] = *(const float4*)&u1b[q * 4];
        }
        if (t < DH) b2s[t] = b2[t];
        __syncthreads();
        for (int idx = t; idx < DH * DH; idx += 256) {
            int k = idx >> 6, j = idx & 63;
            float s = 0.f;
            #pragma unroll 8
            for (int m = 0; m < DH; m++) s = fmaf(W2s[k * DH + m], U1s[m * DH + j], s);
            g_W2U[l * DH * DH + idx] = s;
        }
        if (t < DH) {
            float s = 0.f;
            #pragma unroll 8
            for (int m = 0; m < DH; m++) s = fmaf(b2s[m], U1s[m * DH + t], s);
            g_b2U[l * DH + t] = s;
        }
    } else {
        // composites for layer-0 P/Q from x
        __shared__ __align__(16) float W1s[2 * DH * DH];  // [W1a | W1b]
        __shared__ float iws[3 * DH];
        __shared__ float ibs[DH];
        for (int q = t; q < 2 * DH * DH / 4; q += 256)
            *(float4*)&W1s[q * 4] = *(const float4*)&msg_w1[q * 4];
        if (t < 3 * DH) iws[t] = in_w[t];
        if (t < DH) ibs[t] = in_b[t];
        __syncthreads();
        // CWP[r][j] = sum_k iws[r][k] * W1a[k][j];  CWQ with W1b
        for (int idx = t; idx < 3 * DH; idx += 256) {
            int r = idx >> 6, j = idx & 63;
            float sp = 0.f, sq = 0.f;
            #pragma unroll 8
            for (int k = 0; k < DH; k++) {
                float iv = iws[r * DH + k];
                sp = fmaf(iv, W1s[k * DH + j], sp);
                sq = fmaf(iv, W1s[(DH + k) * DH + j], sq);
            }
            g_CWP[idx] = sp; g_CWQ[idx] = sq;
        }
        if (t < DH) {
            float sp = 0.f, sq = 0.f;
            #pragma unroll 8
            for (int k = 0; k < DH; k++) {
                sp = fmaf(ibs[k], W1s[k * DH + t], sp);
                sq = fmaf(ibs[k], W1s[(DH + k) * DH + t], sq);
            }
            g_cbP[t] = sp; g_cbQ[t] = sq;
        }
    }
}

// =====================================================================
// CSR aggregation: aggH[v] = sum_{e: dst=v} relu(P[src_e] + Q[v] + b1)
// =====================================================================
__global__ void __launch_bounds__(256)
k_agg(const float* __restrict__ b1, int n) {
    int node = blockIdx.x * 16 + (threadIdx.x >> 4);
    int l4 = (threadIdx.x & 15) * 4;
    if (node >= n) return;
    int s = g_off[node], en = g_off[node + 1];
    float4 q = *(const float4*)&g_Q[node * DH + l4];
    float4 b = *(const float4*)&b1[l4];
    q.x += b.x; q.y += b.y; q.z += b.z; q.w += b.w;
    float4 acc = make_float4(0.f, 0.f, 0.f, 0.f);
    int e = s;
    for (; e + 4 <= en; e += 4) {
        int r0 = __ldg(&g_rows[e + 0]);
        int r1 = __ldg(&g_rows[e + 1]);
        int r2 = __ldg(&g_rows[e + 2]);
        int r3 = __ldg(&g_rows[e + 3]);
        float4 p0 = *(const float4*)&g_P[r0 * DH + l4];
        float4 p1 = *(const float4*)&g_P[r1 * DH + l4];
        float4 p2 = *(const float4*)&g_P[r2 * DH + l4];
        float4 p3 = *(const float4*)&g_P[r3 * DH + l4];
        acc.x += fmaxf(p0.x + q.x, 0.f) + fmaxf(p1.x + q.x, 0.f)
               + fmaxf(p2.x + q.x, 0.f) + fmaxf(p3.x + q.x, 0.f);
        acc.y += fmaxf(p0.y + q.y, 0.f) + fmaxf(p1.y + q.y, 0.f)
               + fmaxf(p2.y + q.y, 0.f) + fmaxf(p3.y + q.y, 0.f);
        acc.z += fmaxf(p0.z + q.z, 0.f) + fmaxf(p1.z + q.z, 0.f)
               + fmaxf(p2.z + q.z, 0.f) + fmaxf(p3.z + q.z, 0.f);
        acc.w += fmaxf(p0.w + q.w, 0.f) + fmaxf(p1.w + q.w, 0.f)
               + fmaxf(p2.w + q.w, 0.f) + fmaxf(p3.w + q.w, 0.f);
    }
    for (; e < en; e++) {
        int rr = __ldg(&g_rows[e]);
        float4 p = *(const float4*)&g_P[rr * DH + l4];
        acc.x += fmaxf(p.x + q.x, 0.f);
        acc.y += fmaxf(p.y + q.y, 0.f);
        acc.z += fmaxf(p.z + q.z, 0.f);
        acc.w += fmaxf(p.w + q.w, 0.f);
    }
    *(float4*)&g_aggH[node * DH + l4] = acc;
}

// =====================================================================
// Fused node update (+ next-layer P/Q from the h tile already in smem):
//   pre = h@U1a + aggH@W2U + deg*b2U + ub1 ; h = relu(relu(pre)@U2 + ub2)
//   if w1_next: P = h@W1a', Q = h@W1b'
// =====================================================================
__global__ void __launch_bounds__(256, 4)
k_update(const float* __restrict__ u1a, const float* __restrict__ ub1,
         const float* __restrict__ u2, const float* __restrict__ ub2,
         int l, int n, const float* __restrict__ w1_next) {
    extern __shared__ float sm[];
    float* As   = sm;             // [128][64]
    float* Ws   = sm + 128 * DH;  // [64][64]
    float* b1s  = Ws + 64 * DH;
    float* b2s  = b1s + 64;
    float* b2Us = b2s + 64;
    int t = threadIdx.x;
    int base = blockIdx.x * 128;
    if (t < 64) { b1s[t] = ub1[t]; b2s[t] = ub2[t]; b2Us[t] = g_b2U[l * DH + t]; }

    int tx = t & 15, ty = t >> 4;
    int j0 = tx * 4, i0 = ty * 8;

    float acc[8][4];
    #pragma unroll
    for (int r = 0; r < 8; r++)
        #pragma unroll
        for (int c = 0; c < 4; c++) acc[r][c] = 0.f;

    for (int pass = 0; pass < 2; pass++) {
        __syncthreads();
        const float* a_src = pass ? g_aggH : g_h;
        const float* wsrc  = pass ? (g_W2U + l * DH * DH) : u1a;
        #pragma unroll
        for (int it = 0; it < 8; it++) {
            int q = it * 256 + t;
            int i = q >> 4, j4 = (q & 15) * 4;
            float4 v = make_float4(0.f, 0.f, 0.f, 0.f);
            if (base + i < n) v = *(const float4*)&a_src[(base + i) * DH + j4];
            *(float4*)&As[i * DH + j4] = v;
        }
        STAGE_W(Ws, wsrc, t)
        __syncthreads();

        GEMM_8x4(As, i0, Ws, DH, acc)
    }
    __syncthreads();

    // hid = relu(pre) -> As
    #pragma unroll
    for (int r = 0; r < 8; r++) {
        int i = base + i0 + r;
        float dg = (i < n) ? (float)(g_off[i + 1] - g_off[i]) : 0.f;
        float4 hv;
        hv.x = fmaxf(fmaf(dg, b2Us[j0 + 0], acc[r][0]) + b1s[j0 + 0], 0.f);
        hv.y = fmaxf(fmaf(dg, b2Us[j0 + 1], acc[r][1]) + b1s[j0 + 1], 0.f);
        hv.z = fmaxf(fmaf(dg, b2Us[j0 + 2], acc[r][2]) + b1s[j0 + 2], 0.f);
        hv.w = fmaxf(fmaf(dg, b2Us[j0 + 3], acc[r][3]) + b1s[j0 + 3], 0.f);
        *(float4*)&As[(i0 + r) * DH + j0] = hv;
    }
    STAGE_W(Ws, u2, t)
    __syncthreads();

    float acc2[8][4];
    #pragma unroll
    for (int r = 0; r < 8; r++) {
        acc2[r][0] = b2s[j0 + 0]; acc2[r][1] = b2s[j0 + 1];
        acc2[r][2] = b2s[j0 + 2]; acc2[r][3] = b2s[j0 + 3];
    }

    GEMM_8x4(As, i0, Ws, DH, acc2)

    // h = relu(...) -> gmem + As (for fused P/Q)
    __syncthreads();
    #pragma unroll
    for (int r = 0; r < 8; r++) {
        float4 hv;
        hv.x = fmaxf(acc2[r][0], 0.f); hv.y = fmaxf(acc2[r][1], 0.f);
        hv.z = fmaxf(acc2[r][2], 0.f); hv.w = fmaxf(acc2[r][3], 0.f);
        int i = base + i0 + r;
        if (i < n) *(float4*)&g_h[i * DH + j0] = hv;
        *(float4*)&As[(i0 + r) * DH + j0] = hv;
    }

    if (w1_next) {
        #pragma unroll
        for (int pass = 0; pass < 2; pass++) {
            __syncthreads();
            STAGE_W(Ws, w1_next + pass * 64 * DH, t)
            __syncthreads();
            float acc3[8][4];
            #pragma unroll
            for (int r = 0; r < 8; r++)
                #pragma unroll
                for (int c = 0; c < 4; c++) acc3[r][c] = 0.f;
            GEMM_8x4(As, i0, Ws, DH, acc3)
            float* dst = pass ? g_Q : g_P;
            #pragma unroll
            for (int r = 0; r < 8; r++) {
                int i = base + i0 + r;
                if (i < n)
                    *(float4*)&dst[i * DH + j0] =
                        make_float4(acc3[r][0], acc3[r][1], acc3[r][2], acc3[r][3]);
            }
        }
    }
}

// =====================================================================
// Output: out = h @ out_w + out_b   ([N,64] @ [64,128])
// =====================================================================
__global__ void __launch_bounds__(256, 4)
k_out(const float* __restrict__ ow, const float* __restrict__ ob,
      float* __restrict__ out, int n) {
    extern __shared__ float sm[];
    float* As = sm;            // [64][64]
    float* Ws = sm + 64 * DH;  // [64][128]
    int t = threadIdx.x;
    int base = blockIdx.x * 64;

    #pragma unroll
    for (int it = 0; it < 4; it++) {
        int q = it * 256 + t;
        int i = q >> 4, j4 = (q & 15) * 4;
        float4 v = make_float4(0.f, 0.f, 0.f, 0.f);
        if (base + i < n) v = *(const float4*)&g_h[(base + i) * DH + j4];
        *(float4*)&As[i * DH + j4] = v;
    }
    #pragma unroll
    for (int it = 0; it < 8; it++) {
        int q = it * 256 + t;
        int k = q >> 5, j4 = (q & 31) * 4;
        *(float4*)&Ws[k * 128 + j4] = *(const float4*)&ow[k * 128 + j4];
    }
    __syncthreads();

    int tx = t & 31, ty = t >> 5;
    int j0 = tx * 4, i0 = ty * 8;
    float acc[8][4];
    #pragma unroll
    for (int r = 0; r < 8; r++) {
        acc[r][0] = ob[j0 + 0]; acc[r][1] = ob[j0 + 1];
        acc[r][2] = ob[j0 + 2]; acc[r][3] = ob[j0 + 3];
    }

    GEMM_8x4(As, i0, Ws, 128, acc)

    #pragma unroll
    for (int r = 0; r < 8; r++) {
        int i = base + i0 + r;
        if (i < n)
            *(float4*)&out[i * 128 + j0] =
                make_float4(acc[r][0], acc[r][1], acc[r][2], acc[r][3]);
    }
}

// =====================================================================
// Launcher
// =====================================================================
extern "C" void kernel_launch(void* const* d_in, const int* in_sizes, int n_in,
                              void* d_out, int out_size) {
    const float* x      = (const float*)d_in[0];
    const int*   ei     = (const int*)  d_in[1];
    const float* in_w   = (const float*)d_in[2];
    const float* in_b   = (const float*)d_in[3];
    const float* msg_w1 = (const float*)d_in[4];
    const float* msg_b1 = (const float*)d_in[5];
    const float* msg_w2 = (const float*)d_in[6];
    const float* msg_b2 = (const float*)d_in[7];
    const float* upd_w1 = (const float*)d_in[8];
    const float* upd_b1 = (const float*)d_in[9];
    const float* upd_w2 = (const float*)d_in[10];
    const float* upd_b2 = (const float*)d_in[11];
    const float* out_w  = (const float*)d_in[12];
    const float* out_b  = (const float*)d_in[13];

    int n = in_sizes[0] / 3;
    int e = in_sizes[1] / 2;
    const int* row = ei;
    const int* col = ei + e;

    const int SMEM_UPD = (128 * DH + 64 * DH + 192) * 4;     // 49920
    const int SMEM_OUT = (64 * DH + 64 * 128) * 4;           // 49152

    cudaFuncSetAttribute(k_update, cudaFuncAttributeMaxDynamicSharedMemorySize, SMEM_UPD);
    cudaFuncSetAttribute(k_out,    cudaFuncAttributeMaxDynamicSharedMemorySize, SMEM_OUT);

    // build CSR (sorted by dst) once; reused by all 3 layers
    int nbn = (n + 255) / 256;
    k_zero_hist<<<nbn, 256>>>(n);
    k_hist<<<(e + 255) / 256, 256>>>(col, e);
    k_blocksum<<<nbn, 256>>>(n);
    k_scan_bsum<<<1, 256>>>(nbn);
    k_offsets<<<nbn, 256>>>(n, e);
    k_scatter<<<(e + 255) / 256, 256>>>(row, col, e);

    k_prep_all<<<4, 256>>>(msg_w2, upd_w1, msg_b2, msg_w1, in_w, in_b);
    k_input<<<(n * DH + 255) / 256, 256>>>(x, in_w, in_b, n);

    int nb128 = (n + 127) / 128;
    for (int l = 0; l < 3; l++) {
        k_agg<<<(n + 15) / 16, 256>>>(msg_b1 + l * DH, n);
        const float* w1n = (l < 2) ? (msg_w1 + (l + 1) * 2 * DH * DH) : nullptr;
        k_update<<<nb128, 256, SMEM_UPD>>>(upd_w1 + l * 2 * DH * DH, upd_b1 + l * DH,
                                           upd_w2 + l * DH * DH, upd_b2 + l * DH,
                                           l, n, w1n);
    }
    k_out<<<(n + 63) / 64, 256, SMEM_OUT>>>(out_w, out_b, (float*)d_out, n);
}